// round 15
// baseline (speedup 1.0000x reference)
#include <cuda_runtime.h>
#include <cstddef>
#include <cstdint>

#define TT 4096
#define KK 16
#define BB 32
#define LCH 16
#define NPOS (TT / LCH)            // 256 chunks per batch
#define NCHUNK (BB * NPOS)         // 8192 chunks
#define G8 8
#define NGRP (NPOS / G8)           // 32 S8 groups per batch
#define RHO_C 0.001f
#define NEG_INF_C (-1000000.0f)
#define FLOORP 1e-10f

#define AW_BLOCKS 64
#define AW_TILES ((BB * TT) / (AW_BLOCKS * 128))   // 16 tiles of 128 steps

__device__ float g_S[NCHUNK * 256];        // chunk transfer matrices [chunk][row][col]
__device__ float g_S8[BB * NGRP * 256];    // 8-chunk products
__device__ float g_S64[BB * 4 * 256];      // 64-chunk products
__device__ float g_v8[BB * NGRP * 16];     // alpha at 8-chunk boundaries
__device__ float g_v0[NCHUNK * 16];        // alpha entering each chunk

// 16x16 matvec: y_j = sum_c row_j[c] * u_c (rows as 4 float4), width-16 shfl
__device__ __forceinline__ float mv16(float4 r0, float4 r1, float4 r2, float4 r3,
                                      float u) {
    const unsigned FULL = 0xffffffffu;
    float y0 = 0.f, y1 = 0.f, y2 = 0.f, y3 = 0.f;
    y0 = fmaf(r0.x, __shfl_sync(FULL, u, 0, 16), y0);
    y1 = fmaf(r0.y, __shfl_sync(FULL, u, 1, 16), y1);
    y2 = fmaf(r0.z, __shfl_sync(FULL, u, 2, 16), y2);
    y3 = fmaf(r0.w, __shfl_sync(FULL, u, 3, 16), y3);
    y0 = fmaf(r1.x, __shfl_sync(FULL, u, 4, 16), y0);
    y1 = fmaf(r1.y, __shfl_sync(FULL, u, 5, 16), y1);
    y2 = fmaf(r1.z, __shfl_sync(FULL, u, 6, 16), y2);
    y3 = fmaf(r1.w, __shfl_sync(FULL, u, 7, 16), y3);
    y0 = fmaf(r2.x, __shfl_sync(FULL, u, 8, 16), y0);
    y1 = fmaf(r2.y, __shfl_sync(FULL, u, 9, 16), y1);
    y2 = fmaf(r2.z, __shfl_sync(FULL, u, 10, 16), y2);
    y3 = fmaf(r2.w, __shfl_sync(FULL, u, 11, 16), y3);
    y0 = fmaf(r3.x, __shfl_sync(FULL, u, 12, 16), y0);
    y1 = fmaf(r3.y, __shfl_sync(FULL, u, 13, 16), y1);
    y2 = fmaf(r3.z, __shfl_sync(FULL, u, 14, 16), y2);
    y3 = fmaf(r3.w, __shfl_sync(FULL, u, 15, 16), y3);
    return (y0 + y1) + (y2 + y3);
}

// ---------------------------------------------------------------------------
// Persistent low-occupancy A writer (forked stream). 64 blocks x 128 threads.
// ---------------------------------------------------------------------------
__global__ void __launch_bounds__(128) awrite_kernel(const float* __restrict__ bp,
                                                     float* __restrict__ A) {
    __shared__ float s_cf[128 * 8];
    __shared__ __align__(16) float s_abuf[4][3][4 * 256];
    int tid = threadIdx.x;
    int wid = tid >> 5, lane = tid & 31;

    {
        float4* zp = (float4*)&s_abuf[0][0][0];
        float4 z = make_float4(0.f, 0.f, 0.f, 0.f);
        for (int i = tid; i < 4 * 3 * 4 * 256 / 4; i += 128) zp[i] = z;
    }
    int sl = lane & 15;
    int st2 = lane >> 4;
    int i_dg = (sl == 0) ? 2 : (sl == 15) ? 4 : 3;
    int i_ev = (sl == 0) ? 0 : 1;
    int i_rv = (sl == 15) ? 6 : 5;
    bool has_ev = (sl < 15), has_rv = (sl > 0);

    for (int tile = 0; tile < AW_TILES; ++tile) {
        size_t step0 = (size_t)blockIdx.x * (AW_TILES * 128) + (size_t)tile * 128;
        __syncthreads();
        {
            float bpt = bp[step0 + tid];
            float eta = fminf(fmaxf(0.02f + 0.33f * bpt, 0.001f), 0.95f);
            float stay = fmaxf((1.0f - eta) - RHO_C, 0.01f);
            float rm = (RHO_C + stay) + eta;
            float irm = __fdividef(1.0f, rm);
            float4* cf = (float4*)&s_cf[tid * 8];
            cf[0] = make_float4(eta, eta * irm, (1.0f - eta), stay * irm);
            cf[1] = make_float4((1.0f - RHO_C), RHO_C * irm, RHO_C, 0.0f);
        }
        __syncthreads();

        char* Agbase = (char*)A + (step0 + (size_t)wid * 32) * 1024;
        for (int r = 0; r < 8; ++r) {
            int gr = tile * 8 + r;
            int bufi = gr % 3;
            if (gr >= 3) {
                if (lane == 0)
                    asm volatile("cp.async.bulk.wait_group 2;" ::: "memory");
                __syncwarp();
            }
#pragma unroll
            for (int q = 0; q < 2; ++q) {
                int g = wid * 32 + r * 4 + q * 2 + st2;
                const float* cfb = &s_cf[g * 8];
                float* dst = &s_abuf[wid][bufi][(q * 2 + st2) * 256];
                dst[sl * 17] = cfb[i_dg];
                if (has_ev) dst[sl * 17 + 1] = cfb[i_ev];
                if (has_rv) dst[sl * 17 - 1] = cfb[i_rv];
            }
            __syncwarp();
            asm volatile("fence.proxy.async.shared::cta;" ::: "memory");
            if (lane == 0) {
                uint32_t saddr = (uint32_t)__cvta_generic_to_shared(&s_abuf[wid][bufi][0]);
                asm volatile(
                    "cp.async.bulk.global.shared::cta.bulk_group [%0], [%1], %2;"
                    :: "l"(Agbase + (size_t)r * 4096), "r"(saddr), "r"(4096)
                    : "memory");
                asm volatile("cp.async.bulk.commit_group;" ::: "memory");
            }
        }
    }
    if (lane == 0)
        asm volatile("cp.async.bulk.wait_group 0;" ::: "memory");
}

// ---------------------------------------------------------------------------
// Phase 1: transfer matrices only (LCH=16, 4 warps, 8 chunks per block).
// ---------------------------------------------------------------------------
__global__ void __launch_bounds__(128) phase1_kernel(const float* __restrict__ em,
                                                     const float* __restrict__ bp) {
    __shared__ float s_E[8][LCH * KK];
    __shared__ float s_cf[8][LCH * 8];
    const unsigned FULL = 0xffffffffu;
    int tid = threadIdx.x;
    int wid = tid >> 5, lane = tid & 31;
    int bA = blockIdx.x >> 6;
    int p4 = blockIdx.x & 63;

    for (int ii = tid; ii < 8 * 64; ii += 128) {
        int s = ii >> 6, idx = ii & 63;
        size_t bt = (size_t)(bA + (s & 1) * 16) * TT + (size_t)(4 * p4 + (s >> 1)) * LCH;
        float4 v = ((const float4*)(em + bt * KK))[idx];
        ((float4*)s_E[s])[idx] = make_float4(__expf(v.x), __expf(v.y), __expf(v.z), __expf(v.w));
    }
    {
        int s = tid >> 4, i = tid & 15;
        size_t bt = (size_t)(bA + (s & 1) * 16) * TT + (size_t)(4 * p4 + (s >> 1)) * LCH;
        float bpt = bp[bt + i];
        float eta = fminf(fmaxf(0.02f + 0.33f * bpt, 0.001f), 0.95f);
        float stay = fmaxf((1.0f - eta) - RHO_C, 0.01f);
        float rm = (RHO_C + stay) + eta;
        float irm = __fdividef(1.0f, rm);
        float4* cf = (float4*)&s_cf[s][i * 8];
        cf[0] = make_float4(eta - FLOORP, eta * irm - FLOORP,
                            (1.0f - eta) - FLOORP, stay * irm - FLOORP);
        cf[1] = make_float4((1.0f - RHO_C) - FLOORP, RHO_C * irm - FLOORP,
                            RHO_C - FLOORP, 0.0f);
    }
    __syncthreads();

    int hw = lane >> 4, hl = lane & 15;
    int slot = wid * 2 + hw;
    int b = bA + hw * 16;
    int p = 4 * p4 + wid;

    float w[16];
#pragma unroll
    for (int r = 0; r < 16; r++) w[r] = (r == hl) ? 1.0f : 0.0f;
    float csum = 1.0f;

    int t0 = (p == 0) ? 1 : 0;
    for (int tl = t0; tl < LCH; ++tl) {
        const float4* cf = (const float4*)&s_cf[slot][tl * 8];
        float4 ca = cf[0], cb = cf[1];
        const float* Et = &s_E[slot][tl * KK];
        float y[16];
#pragma unroll
        for (int r = 0; r < 16; r++) {
            float um1 = w[(r + 15) & 15];
            float up1 = w[(r + 1) & 15];
            float ec = (r == 0) ? 0.0f : (r == 1 ? ca.x : ca.y);
            float dc = (r == 0) ? ca.z : (r == 15 ? cb.x : ca.w);
            float rc = (r == 15) ? 0.0f : (r == 14 ? cb.z : cb.y);
            float q = fmaf(dc, w[r], fmaf(rc, up1, ec * um1));
            float P = fmaf(FLOORP, csum, q);
            y[r] = P * Et[r];
        }
        float a0 = (y[0] + y[4]) + (y[8] + y[12]);
        float a1 = (y[1] + y[5]) + (y[9] + y[13]);
        float a2 = (y[2] + y[6]) + (y[10] + y[14]);
        float a3 = (y[3] + y[7]) + (y[11] + y[15]);
        float cs2 = (a0 + a1) + (a2 + a3);
        float sc = __shfl_sync(FULL, cs2, 0, 16);
        float isc = __fdividef(1.0f, sc);
#pragma unroll
        for (int r = 0; r < 16; r++) w[r] = y[r] * isc;
        csum = cs2 * isc;
    }
    float* out = g_S + (size_t)(b * NPOS + p) * 256 + hl;   // [row][col]
#pragma unroll
    for (int r = 0; r < 16; r++) out[r * 16] = w[r];
}

// ---------------------------------------------------------------------------
// Compose (generic): dst[g] = src[8g+7] * ... * src[8g], rescaled per matmul.
// ---------------------------------------------------------------------------
__global__ void __launch_bounds__(256) compose_kernel(const float* __restrict__ src,
                                                      float* __restrict__ dst) {
    __shared__ float sM[8][256];
    __shared__ float sbuf[2][256];
    int tid = threadIdx.x;
    const float* S0 = src + (size_t)blockIdx.x * 8 * 256;
#pragma unroll
    for (int m = 0; m < 8; m++) sM[m][tid] = S0[m * 256 + tid];
    __syncthreads();

    int r = tid >> 4, c = tid & 15;
    float acc = 0.0f;
#pragma unroll
    for (int k = 0; k < 16; k++) acc = fmaf(sM[1][r * 16 + k], sM[0][k * 16 + c], acc);
    sbuf[0][tid] = acc;
    __syncthreads();
    int cur = 0;
#pragma unroll
    for (int m = 2; m < 8; m++) {
        float inv = __fdividef(1.0f, sbuf[cur][0]);
        acc = 0.0f;
#pragma unroll
        for (int k = 0; k < 16; k++) acc = fmaf(sM[m][r * 16 + k], sbuf[cur][k * 16 + c], acc);
        acc *= inv;
        if (m == 7) break;
        sbuf[1 - cur][tid] = acc;
        __syncthreads();
        cur ^= 1;
    }
    dst[(size_t)blockIdx.x * 256 + tid] = acc;
}

// ---------------------------------------------------------------------------
// Phase 2ab: per batch. Warp 0: 3-step serial chain over S64 -> starts at
// 64-boundaries (smem). Then 4 half-warps each run 7 matvecs over S8 to
// produce all 32 8-boundary alphas (g_v8).
// ---------------------------------------------------------------------------
__global__ void __launch_bounds__(64) phase2ab_kernel(const float* __restrict__ em,
                                                      const float* __restrict__ mk) {
    __shared__ float s_vq[4][16];
    const unsigned FULL = 0xffffffffu;
    int b = blockIdx.x;
    int tid = threadIdx.x;
    int j = tid & 15;

    if (tid < 32) {
        float em0 = __ldg(em + (size_t)b * TT * KK);
        float emj = __ldg(em + (size_t)b * TT * KK + j);
        float m0 = __ldg(mk + (size_t)b * TT);
        float la0 = (j == 0) ? 0.0f : (NEG_INF_C + emj - em0);
        la0 = m0 * la0 + (1.0f - m0) * ((j == 0) ? 0.0f : NEG_INF_C);
        float u = expf(la0);
        if (tid < 16) s_vq[0][j] = u;
#pragma unroll
        for (int k = 0; k < 3; ++k) {
            const float4* row = (const float4*)(g_S64 + ((size_t)b * 4 + k) * 256 + j * 16);
            float y = mv16(row[0], row[1], row[2], row[3], u);
            float ya = __shfl_sync(FULL, y, 0, 16);
            u = y * __fdividef(1.0f, ya);
            if (tid < 16) s_vq[k + 1][j] = u;
        }
    }
    __syncthreads();

    int hw = tid >> 4;    // 0..3
    float u = s_vq[hw][j];
    g_v8[((size_t)b * NGRP + hw * 8) * 16 + j] = u;
    const float4* src = (const float4*)(g_S8 + ((size_t)b * NGRP + hw * 8) * 256 + j * 16);
    float4 w0 = src[0], w1 = src[1], w2 = src[2], w3 = src[3];
#pragma unroll
    for (int s = 0; s < 7; ++s) {
        float4 c0 = w0, c1 = w1, c2 = w2, c3 = w3;
        if (s < 6) {
            const float4* nx = (const float4*)(g_S8 + ((size_t)b * NGRP + hw * 8 + s + 1) * 256 + j * 16);
            w0 = nx[0]; w1 = nx[1]; w2 = nx[2]; w3 = nx[3];
        }
        float y = mv16(c0, c1, c2, c3, u);
        float ya = __shfl_sync(FULL, y, 0, 16);
        u = y * __fdividef(1.0f, ya);
        g_v8[((size_t)b * NGRP + hw * 8 + s + 1) * 16 + j] = u;
    }
}

// ---------------------------------------------------------------------------
// Phase 2c: 1024 independent half-warp tasks; task (b,g8) runs 7 matvecs over
// chunk matrices S to fill chunk starts g_v0 for positions 8*g8 .. 8*g8+7.
// ---------------------------------------------------------------------------
__global__ void __launch_bounds__(256) phase2c_kernel() {
    const unsigned FULL = 0xffffffffu;
    int task = blockIdx.x * 16 + (threadIdx.x >> 4);   // = b*NGRP + g8
    int j = threadIdx.x & 15;
    int b = task >> 5, g8 = task & 31;
    size_t cbase = (size_t)b * NPOS + g8 * 8;

    float u = g_v8[(size_t)task * 16 + j];
    g_v0[cbase * 16 + j] = u;
    const float4* src = (const float4*)(g_S + cbase * 256 + j * 16);
    float4 w0 = src[0], w1 = src[1], w2 = src[2], w3 = src[3];
#pragma unroll
    for (int s = 0; s < 7; ++s) {
        float4 c0 = w0, c1 = w1, c2 = w2, c3 = w3;
        if (s < 6) {
            const float4* nx = (const float4*)(g_S + (cbase + s + 1) * 256 + j * 16);
            w0 = nx[0]; w1 = nx[1]; w2 = nx[2]; w3 = nx[3];
        }
        float y = mv16(c0, c1, c2, c3, u);
        float ya = __shfl_sync(FULL, y, 0, 16);
        u = y * __fdividef(1.0f, ya);
        g_v0[(cbase + s + 1) * 16 + j] = u;
    }
}

// ---------------------------------------------------------------------------
// Phase 3: re-scan only. Block = 2 warps; warp w scans chunks
// (bA,2p2+w),(bA+16,2p2+w) in its half-warps.
// ---------------------------------------------------------------------------
__global__ void __launch_bounds__(64) phase3_kernel(
    const float* __restrict__ em, const float* __restrict__ bp,
    const float* __restrict__ mk,
    float* __restrict__ bel, float* __restrict__ lbel, float* __restrict__ lnr)
{
    __shared__ float s_E[4][LCH * KK];
    __shared__ float s_cf[4][LCH * 8];
    __shared__ float s_mk[4][LCH];
    const unsigned FULL = 0xffffffffu;
    int tid = threadIdx.x;
    int wid = tid >> 5, lane = tid & 31;
    int bA = blockIdx.x >> 7;
    int p2 = blockIdx.x & 127;

    for (int ii = tid; ii < 4 * 64; ii += 64) {
        int s = ii >> 6, idx = ii & 63;
        size_t bt = (size_t)(bA + (s & 1) * 16) * TT + (size_t)(2 * p2 + (s >> 1)) * LCH;
        float4 v = ((const float4*)(em + bt * KK))[idx];
        ((float4*)s_E[s])[idx] = make_float4(__expf(v.x), __expf(v.y), __expf(v.z), __expf(v.w));
    }
    {
        int s0 = tid >> 4, i = tid & 15;
        size_t bt = (size_t)(bA + (s0 & 1) * 16) * TT + (size_t)(2 * p2 + (s0 >> 1)) * LCH;
        float bpt = bp[bt + i];
        float eta = fminf(fmaxf(0.02f + 0.33f * bpt, 0.001f), 0.95f);
        float stay = fmaxf((1.0f - eta) - RHO_C, 0.01f);
        float rm = (RHO_C + stay) + eta;
        float irm = __fdividef(1.0f, rm);
        float4* cf = (float4*)&s_cf[s0][i * 8];
        cf[0] = make_float4(eta - FLOORP, eta * irm - FLOORP,
                            (1.0f - eta) - FLOORP, stay * irm - FLOORP);
        cf[1] = make_float4((1.0f - RHO_C) - FLOORP, RHO_C * irm - FLOORP,
                            RHO_C - FLOORP, 0.0f);
        s_mk[s0][i] = mk[bt + i];
    }
    __syncthreads();

    int hw = lane >> 4, j = lane & 15;
    int slot = wid * 2 + hw;
    int b = bA + hw * 16;
    int p = 2 * p2 + wid;
    size_t base_t = (size_t)b * TT + (size_t)p * LCH;

    float* belb  = bel  + base_t * KK;
    float* lbelb = lbel + base_t * KK;
    float* lnrb  = lnr  + base_t;

    float w;
    int t0;
    if (p == 0) {
        float em0 = __ldg(em + (size_t)b * TT * KK);
        float emj = __ldg(em + (size_t)b * TT * KK + j);
        float m0 = s_mk[slot][0];
        float la0 = (j == 0) ? 0.0f : (NEG_INF_C + emj - em0);
        la0 = m0 * la0 + (1.0f - m0) * ((j == 0) ? 0.0f : NEG_INF_C);
        w = expf(la0);
        belb[j] = w;
        lbelb[j] = la0;
        if (j == 0) lnrb[0] = m0 * em0;    // lZ0 == em[b,0,0] exactly
        t0 = 1;
    } else {
        w = g_v0[(size_t)(b * NPOS + p) * 16 + j];
        t0 = 0;
    }

    for (int tl = t0; tl < LCH; ++tl) {
        const float4* cf = (const float4*)&s_cf[slot][tl * 8];
        float4 ca = cf[0], cb = cf[1];
        float E = s_E[slot][tl * KK + j];

        float c = w;
#pragma unroll
        for (int s = 8; s >= 1; s >>= 1)
            c += __shfl_xor_sync(FULL, c, s, 16);
        float ic = __fdividef(1.0f, c);

        float um1 = __shfl_sync(FULL, w, (j + 15) & 15, 16);
        float up1 = __shfl_sync(FULL, w, (j + 1) & 15, 16);
        float ec = (j == 0) ? 0.0f : (j == 1 ? ca.x : ca.y);
        float dc = (j == 0) ? ca.z : (j == 15 ? cb.x : ca.w);
        float rc = (j == 15) ? 0.0f : (j == 14 ? cb.z : cb.y);
        float q = fmaf(dc, w, fmaf(rc, up1, ec * um1));
        float wn = fmaf(ic, q, FLOORP) * E;

        if (tl > t0) {
            float lZ = __logf(c);
            belb[(tl - 1) * KK + j]  = w * ic;
            lbelb[(tl - 1) * KK + j] = __logf(w) - lZ;
            if (j == 0) lnrb[tl - 1] = s_mk[slot][tl - 1] * lZ;
        }
        w = wn;
    }
    float c = w;
#pragma unroll
    for (int s = 8; s >= 1; s >>= 1)
        c += __shfl_xor_sync(FULL, c, s, 16);
    float ic = __fdividef(1.0f, c);
    float lZ = __logf(c);
    belb[(LCH - 1) * KK + j]  = w * ic;
    lbelb[(LCH - 1) * KK + j] = __logf(w) - lZ;
    if (j == 0) lnrb[LCH - 1] = s_mk[slot][LCH - 1] * lZ;
}

// ---------------------------------------------------------------------------
extern "C" void kernel_launch(void* const* d_in, const int* in_sizes, int n_in,
                              void* d_out, int out_size) {
    const float* em = (const float*)d_in[0];
    const float* bp = (const float*)d_in[1];
    const float* mk = (const float*)d_in[2];
    float* out = (float*)d_out;

    const size_t BTK = (size_t)BB * TT * KK;
    const size_t BT  = (size_t)BB * TT;
    float* bel  = out;
    float* lbel = out + BTK;
    float* lnr  = out + 2 * BTK;
    float* A    = out + 2 * BTK + BT;

    float* dS;   cudaGetSymbolAddress((void**)&dS, g_S);
    float* dS8;  cudaGetSymbolAddress((void**)&dS8, g_S8);
    float* dS64; cudaGetSymbolAddress((void**)&dS64, g_S64);

    cudaStream_t s2;
    cudaEvent_t evFork, evJoin;
    cudaStreamCreateWithFlags(&s2, cudaStreamNonBlocking);
    cudaEventCreateWithFlags(&evFork, cudaEventDisableTiming);
    cudaEventCreateWithFlags(&evJoin, cudaEventDisableTiming);

    cudaEventRecord(evFork, 0);
    cudaStreamWaitEvent(s2, evFork, 0);
    awrite_kernel<<<AW_BLOCKS, 128, 0, s2>>>(bp, A);
    cudaEventRecord(evJoin, s2);

    phase1_kernel<<<16 * 64, 128>>>(em, bp);
    compose_kernel<<<BB * NGRP, 256>>>(dS, dS8);       // S   -> S8
    compose_kernel<<<BB * 4, 256>>>(dS8, dS64);        // S8  -> S64
    phase2ab_kernel<<<BB, 64>>>(em, mk);
    phase2c_kernel<<<BB * NGRP / 16, 256>>>();
    phase3_kernel<<<16 * 128, 64>>>(em, bp, mk, bel, lbel, lnr);

    cudaStreamWaitEvent(0, evJoin, 0);
}